// round 3
// baseline (speedup 1.0000x reference)
#include <cuda_runtime.h>

#define C       128
#define C4      32       // C/4 float4s per row
#define PEDIM   8
#define NG      512
#define LAYERS  3
#define BN_EPS  1e-5f
#define N_MAX   100352
#define E_MAX   1605632

// ---------------- scratch (static device globals; no allocation) ----------------
__device__ float g_h[(size_t)N_MAX * C];
__device__ float g_t[(size_t)N_MAX * C];
__device__ float g_agg[(size_t)N_MAX * C];
__device__ int   g_deg[N_MAX];
__device__ int   g_fill[N_MAX];
__device__ float g_dinv[N_MAX];
__device__ int   g_csr_ptr[N_MAX + 1];
__device__ int   g_csr_col[E_MAX];
__device__ float g_csr_norm[E_MAX];
__device__ float g_bnsum[C];
__device__ float g_bnsq[C];
__device__ float g_scale[C];
__device__ float g_shift[C];
__device__ int   g_gcount[NG];
__device__ int   g_goff[NG];
__device__ float g_pooled[NG * C];
__device__ int   g_idx64;

// ---------------- helpers ----------------
__device__ __forceinline__ int load_idx(const void* p, long long i) {
    if (g_idx64) return (int)((const long long*)p)[i];
    return ((const int*)p)[i];
}

// detect whether index tensors are int64 (high 32-bit words all zero) or int32
__global__ void k_detect(const unsigned int* w) {
    if (threadIdx.x == 0 && blockIdx.x == 0) {
        int z = 0;
        for (int i = 0; i < 64; i++) if (w[2 * i + 1] == 0u) z++;
        g_idx64 = (z >= 48) ? 1 : 0;
    }
}

__global__ void k_zero(int N) {
    int stride = gridDim.x * blockDim.x;
    for (int i = blockIdx.x * blockDim.x + threadIdx.x; i < N; i += stride) {
        g_deg[i] = 0; g_fill[i] = 0;
    }
    for (int i = blockIdx.x * blockDim.x + threadIdx.x; i < NG; i += stride) {
        g_gcount[i] = 0;
    }
}

__global__ void k_deg(const void* ei, int E) {
    int stride = gridDim.x * blockDim.x;
    for (int e = blockIdx.x * blockDim.x + threadIdx.x; e < E; e += stride) {
        int r = load_idx(ei, e);
        atomicAdd(&g_deg[r], 1);
    }
}

__global__ void k_gcount(const void* batch, int N) {
    int stride = gridDim.x * blockDim.x;
    for (int i = blockIdx.x * blockDim.x + threadIdx.x; i < N; i += stride) {
        int g = load_idx(batch, i);
        atomicAdd(&g_gcount[g], 1);
    }
}

// single-block scan over node degrees -> csr_ptr; also computes dinv
__global__ void k_scan(int N) {
    __shared__ int ssum[1024];
    int t = threadIdx.x;
    int chunk = (N + 1023) >> 10;
    int lo = t * chunk;
    int hi = lo + chunk; if (hi > N) hi = N; if (lo > N) lo = N;
    int s = 0;
    for (int i = lo; i < hi; i++) {
        int d = g_deg[i];
        s += d;
        g_dinv[i] = (d > 0) ? rsqrtf((float)d) : 0.f;
    }
    ssum[t] = s;
    __syncthreads();
    for (int off = 1; off < 1024; off <<= 1) {
        int v = (t >= off) ? ssum[t - off] : 0;
        __syncthreads();
        ssum[t] += v;
        __syncthreads();
    }
    int run = (t == 0) ? 0 : ssum[t - 1];
    for (int i = lo; i < hi; i++) {
        g_csr_ptr[i] = run;
        run += g_deg[i];
    }
    if (t == 0) g_csr_ptr[N] = ssum[1023];
}

__global__ void k_gscan() {
    __shared__ int s[NG];
    int t = threadIdx.x;
    s[t] = g_gcount[t];
    __syncthreads();
    for (int off = 1; off < NG; off <<= 1) {
        int v = (t >= off) ? s[t - off] : 0;
        __syncthreads();
        s[t] += v;
        __syncthreads();
    }
    g_goff[t] = (t == 0) ? 0 : s[t - 1];
}

__global__ void k_csrfill(const void* ei, int E) {
    int stride = gridDim.x * blockDim.x;
    for (int e = blockIdx.x * blockDim.x + threadIdx.x; e < E; e += stride) {
        int r = load_idx(ei, e);
        int c = load_idx(ei, (long long)E + e);
        int pos = g_csr_ptr[r] + atomicAdd(&g_fill[r], 1);
        g_csr_col[pos] = c;
        g_csr_norm[pos] = g_dinv[r] * g_dinv[c];
    }
}

// h0 = x @ node_W + node_b + pe @ pe_W + pe_b
__global__ void k_encode(const float* __restrict__ x, const float* __restrict__ pe,
                         const float* __restrict__ nW, const float* __restrict__ nb,
                         const float* __restrict__ pW, const float* __restrict__ pb, int N) {
    const float4* nW4 = (const float4*)nW;
    const float4* nb4 = (const float4*)nb;
    const float4* pW4 = (const float4*)pW;
    const float4* pb4 = (const float4*)pb;
    float4* H4 = (float4*)g_h;
    int total = N * C4;
    int stride = gridDim.x * blockDim.x;
    for (int i = blockIdx.x * blockDim.x + threadIdx.x; i < total; i += stride) {
        int n = i >> 5, q = i & 31;
        float xv = __ldg(&x[n]);
        float4 b0 = __ldg(&nb4[q]);
        float4 b1 = __ldg(&pb4[q]);
        float4 w  = __ldg(&nW4[q]);
        float4 a;
        a.x = b0.x + b1.x + xv * w.x;
        a.y = b0.y + b1.y + xv * w.y;
        a.z = b0.z + b1.z + xv * w.z;
        a.w = b0.w + b1.w + xv * w.w;
        #pragma unroll
        for (int k = 0; k < PEDIM; k++) {
            float pv = __ldg(&pe[(size_t)n * PEDIM + k]);
            float4 pw = __ldg(&pW4[k * C4 + q]);
            a.x = fmaf(pv, pw.x, a.x);
            a.y = fmaf(pv, pw.y, a.y);
            a.z = fmaf(pv, pw.z, a.z);
            a.w = fmaf(pv, pw.w, a.w);
        }
        H4[i] = a;
    }
}

// t = h @ W   (no bias; bias added during aggregation)
// W kept in dynamic SMEM (64KB). 4-row register blocking per warp: each smem
// W load is reused across 4 output rows -> FMA-pipe-bound, not smem-bound.
__global__ void __launch_bounds__(256) k_gemm(const float* __restrict__ W, int N) {
    extern __shared__ float Ws[];
    const float4* W4 = (const float4*)W;
    float4* Ws4 = (float4*)Ws;
    for (int i = threadIdx.x; i < C * C4; i += 256) Ws4[i] = __ldg(&W4[i]);
    __syncthreads();
    int warp = threadIdx.x >> 5, lane = threadIdx.x & 31;
    int warps_total = gridDim.x * 8;
    const float4* A4 = (const float4*)g_h;
    float4* T4 = (float4*)g_t;

    for (int r0 = (blockIdx.x * 8 + warp) * 4; r0 < N; r0 += warps_total * 4) {
        int nr = N - r0; if (nr > 4) nr = 4;
        const float4* Ar0 = A4 + (size_t)r0 * C4;
        float4 acc0 = make_float4(0.f, 0.f, 0.f, 0.f);
        float4 acc1 = acc0, acc2 = acc0, acc3 = acc0;
        if (nr == 4) {
            #pragma unroll
            for (int kk = 0; kk < 32; kk++) {
                float4 a0 = __ldg(&Ar0[kk]);
                float4 a1 = __ldg(&Ar0[C4 + kk]);
                float4 a2 = __ldg(&Ar0[2 * C4 + kk]);
                float4 a3 = __ldg(&Ar0[3 * C4 + kk]);
                const float4* wr = Ws4 + (kk * 4) * C4 + lane;
                float4 w0 = wr[0 * C4];
                float4 w1 = wr[1 * C4];
                float4 w2 = wr[2 * C4];
                float4 w3 = wr[3 * C4];
                acc0.x = fmaf(a0.x, w0.x, acc0.x); acc0.x = fmaf(a0.y, w1.x, acc0.x);
                acc0.x = fmaf(a0.z, w2.x, acc0.x); acc0.x = fmaf(a0.w, w3.x, acc0.x);
                acc0.y = fmaf(a0.x, w0.y, acc0.y); acc0.y = fmaf(a0.y, w1.y, acc0.y);
                acc0.y = fmaf(a0.z, w2.y, acc0.y); acc0.y = fmaf(a0.w, w3.y, acc0.y);
                acc0.z = fmaf(a0.x, w0.z, acc0.z); acc0.z = fmaf(a0.y, w1.z, acc0.z);
                acc0.z = fmaf(a0.z, w2.z, acc0.z); acc0.z = fmaf(a0.w, w3.z, acc0.z);
                acc0.w = fmaf(a0.x, w0.w, acc0.w); acc0.w = fmaf(a0.y, w1.w, acc0.w);
                acc0.w = fmaf(a0.z, w2.w, acc0.w); acc0.w = fmaf(a0.w, w3.w, acc0.w);

                acc1.x = fmaf(a1.x, w0.x, acc1.x); acc1.x = fmaf(a1.y, w1.x, acc1.x);
                acc1.x = fmaf(a1.z, w2.x, acc1.x); acc1.x = fmaf(a1.w, w3.x, acc1.x);
                acc1.y = fmaf(a1.x, w0.y, acc1.y); acc1.y = fmaf(a1.y, w1.y, acc1.y);
                acc1.y = fmaf(a1.z, w2.y, acc1.y); acc1.y = fmaf(a1.w, w3.y, acc1.y);
                acc1.z = fmaf(a1.x, w0.z, acc1.z); acc1.z = fmaf(a1.y, w1.z, acc1.z);
                acc1.z = fmaf(a1.z, w2.z, acc1.z); acc1.z = fmaf(a1.w, w3.z, acc1.z);
                acc1.w = fmaf(a1.x, w0.w, acc1.w); acc1.w = fmaf(a1.y, w1.w, acc1.w);
                acc1.w = fmaf(a1.z, w2.w, acc1.w); acc1.w = fmaf(a1.w, w3.w, acc1.w);

                acc2.x = fmaf(a2.x, w0.x, acc2.x); acc2.x = fmaf(a2.y, w1.x, acc2.x);
                acc2.x = fmaf(a2.z, w2.x, acc2.x); acc2.x = fmaf(a2.w, w3.x, acc2.x);
                acc2.y = fmaf(a2.x, w0.y, acc2.y); acc2.y = fmaf(a2.y, w1.y, acc2.y);
                acc2.y = fmaf(a2.z, w2.y, acc2.y); acc2.y = fmaf(a2.w, w3.y, acc2.y);
                acc2.z = fmaf(a2.x, w0.z, acc2.z); acc2.z = fmaf(a2.y, w1.z, acc2.z);
                acc2.z = fmaf(a2.z, w2.z, acc2.z); acc2.z = fmaf(a2.w, w3.z, acc2.z);
                acc2.w = fmaf(a2.x, w0.w, acc2.w); acc2.w = fmaf(a2.y, w1.w, acc2.w);
                acc2.w = fmaf(a2.z, w2.w, acc2.w); acc2.w = fmaf(a2.w, w3.w, acc2.w);

                acc3.x = fmaf(a3.x, w0.x, acc3.x); acc3.x = fmaf(a3.y, w1.x, acc3.x);
                acc3.x = fmaf(a3.z, w2.x, acc3.x); acc3.x = fmaf(a3.w, w3.x, acc3.x);
                acc3.y = fmaf(a3.x, w0.y, acc3.y); acc3.y = fmaf(a3.y, w1.y, acc3.y);
                acc3.y = fmaf(a3.z, w2.y, acc3.y); acc3.y = fmaf(a3.w, w3.y, acc3.y);
                acc3.z = fmaf(a3.x, w0.z, acc3.z); acc3.z = fmaf(a3.y, w1.z, acc3.z);
                acc3.z = fmaf(a3.z, w2.z, acc3.z); acc3.z = fmaf(a3.w, w3.z, acc3.z);
                acc3.w = fmaf(a3.x, w0.w, acc3.w); acc3.w = fmaf(a3.y, w1.w, acc3.w);
                acc3.w = fmaf(a3.z, w2.w, acc3.w); acc3.w = fmaf(a3.w, w3.w, acc3.w);
            }
            T4[(size_t)r0 * C4 + lane] = acc0;
            T4[(size_t)(r0 + 1) * C4 + lane] = acc1;
            T4[(size_t)(r0 + 2) * C4 + lane] = acc2;
            T4[(size_t)(r0 + 3) * C4 + lane] = acc3;
        } else {
            for (int i = 0; i < nr; i++) {
                const float4* Arow = Ar0 + (size_t)i * C4;
                float4 acc = make_float4(0.f, 0.f, 0.f, 0.f);
                #pragma unroll
                for (int kk = 0; kk < 32; kk++) {
                    float4 av = __ldg(&Arow[kk]);
                    const float4* wr = Ws4 + (kk * 4) * C4 + lane;
                    float4 w0 = wr[0 * C4];
                    float4 w1 = wr[1 * C4];
                    float4 w2 = wr[2 * C4];
                    float4 w3 = wr[3 * C4];
                    acc.x = fmaf(av.x, w0.x, acc.x); acc.x = fmaf(av.y, w1.x, acc.x);
                    acc.x = fmaf(av.z, w2.x, acc.x); acc.x = fmaf(av.w, w3.x, acc.x);
                    acc.y = fmaf(av.x, w0.y, acc.y); acc.y = fmaf(av.y, w1.y, acc.y);
                    acc.y = fmaf(av.z, w2.y, acc.y); acc.y = fmaf(av.w, w3.y, acc.y);
                    acc.z = fmaf(av.x, w0.z, acc.z); acc.z = fmaf(av.y, w1.z, acc.z);
                    acc.z = fmaf(av.z, w2.z, acc.z); acc.z = fmaf(av.w, w3.z, acc.z);
                    acc.w = fmaf(av.x, w0.w, acc.w); acc.w = fmaf(av.y, w1.w, acc.w);
                    acc.w = fmaf(av.z, w2.w, acc.w); acc.w = fmaf(av.w, w3.w, acc.w);
                }
                T4[(size_t)(r0 + i) * C4 + lane] = acc;
            }
        }
    }
}

__global__ void k_zerobn() {
    if (threadIdx.x < C) { g_bnsum[threadIdx.x] = 0.f; g_bnsq[threadIdx.x] = 0.f; }
}

// agg[n] = t[n] + b + sum_{edges into n} norm * t[col]; fused BN partial stats
__global__ void __launch_bounds__(256) k_aggregate(const float* __restrict__ bias, int N) {
    __shared__ float ssum[C];
    __shared__ float ssq[C];
    if (threadIdx.x < C) { ssum[threadIdx.x] = 0.f; ssq[threadIdx.x] = 0.f; }
    __syncthreads();

    int warp = threadIdx.x >> 5, lane = threadIdx.x & 31;
    int warps_total = gridDim.x * 8;
    const float4* T4 = (const float4*)g_t;
    float4* A4 = (float4*)g_agg;
    float4 bias4 = __ldg(&((const float4*)bias)[lane]);

    float4 ps = make_float4(0.f, 0.f, 0.f, 0.f);
    float4 pq = make_float4(0.f, 0.f, 0.f, 0.f);

    for (int n = blockIdx.x * 8 + warp; n < N; n += warps_total) {
        int s = g_csr_ptr[n], e = g_csr_ptr[n + 1];
        float4 acc = __ldg(&T4[(size_t)n * C4 + lane]);
        acc.x += bias4.x; acc.y += bias4.y; acc.z += bias4.z; acc.w += bias4.w;
        int j = s;
        for (; j + 4 <= e; j += 4) {
            int   c0 = __ldg(&g_csr_col[j]);
            int   c1 = __ldg(&g_csr_col[j + 1]);
            int   c2 = __ldg(&g_csr_col[j + 2]);
            int   c3 = __ldg(&g_csr_col[j + 3]);
            float w0 = __ldg(&g_csr_norm[j]);
            float w1 = __ldg(&g_csr_norm[j + 1]);
            float w2 = __ldg(&g_csr_norm[j + 2]);
            float w3 = __ldg(&g_csr_norm[j + 3]);
            float4 t0 = __ldg(&T4[(size_t)c0 * C4 + lane]);
            float4 t1 = __ldg(&T4[(size_t)c1 * C4 + lane]);
            float4 t2 = __ldg(&T4[(size_t)c2 * C4 + lane]);
            float4 t3 = __ldg(&T4[(size_t)c3 * C4 + lane]);
            acc.x = fmaf(w0, t0.x, acc.x); acc.y = fmaf(w0, t0.y, acc.y);
            acc.z = fmaf(w0, t0.z, acc.z); acc.w = fmaf(w0, t0.w, acc.w);
            acc.x = fmaf(w1, t1.x, acc.x); acc.y = fmaf(w1, t1.y, acc.y);
            acc.z = fmaf(w1, t1.z, acc.z); acc.w = fmaf(w1, t1.w, acc.w);
            acc.x = fmaf(w2, t2.x, acc.x); acc.y = fmaf(w2, t2.y, acc.y);
            acc.z = fmaf(w2, t2.z, acc.z); acc.w = fmaf(w2, t2.w, acc.w);
            acc.x = fmaf(w3, t3.x, acc.x); acc.y = fmaf(w3, t3.y, acc.y);
            acc.z = fmaf(w3, t3.z, acc.z); acc.w = fmaf(w3, t3.w, acc.w);
        }
        for (; j < e; j++) {
            int   ci = __ldg(&g_csr_col[j]);
            float w  = __ldg(&g_csr_norm[j]);
            float4 tv = __ldg(&T4[(size_t)ci * C4 + lane]);
            acc.x = fmaf(w, tv.x, acc.x); acc.y = fmaf(w, tv.y, acc.y);
            acc.z = fmaf(w, tv.z, acc.z); acc.w = fmaf(w, tv.w, acc.w);
        }
        A4[(size_t)n * C4 + lane] = acc;
        ps.x += acc.x; ps.y += acc.y; ps.z += acc.z; ps.w += acc.w;
        pq.x = fmaf(acc.x, acc.x, pq.x); pq.y = fmaf(acc.y, acc.y, pq.y);
        pq.z = fmaf(acc.z, acc.z, pq.z); pq.w = fmaf(acc.w, acc.w, pq.w);
    }
    int c0 = lane * 4;
    atomicAdd(&ssum[c0 + 0], ps.x); atomicAdd(&ssum[c0 + 1], ps.y);
    atomicAdd(&ssum[c0 + 2], ps.z); atomicAdd(&ssum[c0 + 3], ps.w);
    atomicAdd(&ssq[c0 + 0], pq.x);  atomicAdd(&ssq[c0 + 1], pq.y);
    atomicAdd(&ssq[c0 + 2], pq.z);  atomicAdd(&ssq[c0 + 3], pq.w);
    __syncthreads();
    if (threadIdx.x < C) {
        atomicAdd(&g_bnsum[threadIdx.x], ssum[threadIdx.x]);
        atomicAdd(&g_bnsq[threadIdx.x],  ssq[threadIdx.x]);
    }
}

__global__ void k_bnfinal(const float* __restrict__ gamma, const float* __restrict__ beta, int N) {
    int c = threadIdx.x;
    if (c < C) {
        float invN = 1.f / (float)N;
        float mu = g_bnsum[c] * invN;
        float var = g_bnsq[c] * invN - mu * mu;
        if (var < 0.f) var = 0.f;
        float a = __ldg(&gamma[c]) * rsqrtf(var + BN_EPS);
        g_scale[c] = a;
        g_shift[c] = __ldg(&beta[c]) - mu * a;
    }
}

// h += relu(agg * scale + shift)
__global__ void k_update(int N) {
    const float4* A4 = (const float4*)g_agg;
    float4* H4 = (float4*)g_h;
    const float4* sc4 = (const float4*)g_scale;
    const float4* sh4 = (const float4*)g_shift;
    int total = N * C4;
    int stride = gridDim.x * blockDim.x;
    for (int i = blockIdx.x * blockDim.x + threadIdx.x; i < total; i += stride) {
        int q = i & 31;
        float4 a = __ldg(&sc4[q]);
        float4 s = __ldg(&sh4[q]);
        float4 av = A4[i];
        float4 hv = H4[i];
        float rx = fmaf(av.x, a.x, s.x);
        float ry = fmaf(av.y, a.y, s.y);
        float rz = fmaf(av.z, a.z, s.z);
        float rw = fmaf(av.w, a.w, s.w);
        hv.x += rx > 0.f ? rx : 0.f;
        hv.y += ry > 0.f ? ry : 0.f;
        hv.z += rz > 0.f ? rz : 0.f;
        hv.w += rw > 0.f ? rw : 0.f;
        H4[i] = hv;
    }
}

// per-graph mean pooling (batch sorted -> contiguous node ranges)
__global__ void k_pool(int N) {
    int g = blockIdx.x;
    int c = threadIdx.x;
    int start = g_goff[g];
    int cnt = g_gcount[g];
    float s = 0.f;
    const float* H = g_h;
    for (int i = 0; i < cnt; i++) {
        s += H[(size_t)(start + i) * C + c];
    }
    g_pooled[g * C + c] = s / fmaxf((float)cnt, 1.f);
}

// out[g] = relu(pooled @ W1 + b1) @ W2 + b2
__global__ void k_head(const float* __restrict__ W1, const float* __restrict__ b1,
                       const float* __restrict__ W2, const float* __restrict__ b2,
                       float* __restrict__ out) {
    __shared__ float sp[C];
    __shared__ float red[4];
    int g = blockIdx.x;
    int j = threadIdx.x;
    sp[j] = g_pooled[g * C + j];
    __syncthreads();
    float acc = __ldg(&b1[j]);
    #pragma unroll 8
    for (int k = 0; k < C; k++) {
        acc = fmaf(sp[k], __ldg(&W1[k * C + j]), acc);
    }
    float hid = acc > 0.f ? acc : 0.f;
    float v = hid * __ldg(&W2[j]);
    #pragma unroll
    for (int o = 16; o > 0; o >>= 1) v += __shfl_down_sync(0xffffffffu, v, o);
    if ((j & 31) == 0) red[j >> 5] = v;
    __syncthreads();
    if (j == 0) out[g] = red[0] + red[1] + red[2] + red[3] + __ldg(&b2[0]);
}

// ---------------- launch ----------------
extern "C" void kernel_launch(void* const* d_in, const int* in_sizes, int n_in,
                              void* d_out, int out_size) {
    const float* x      = (const float*)d_in[0];
    const float* pe     = (const float*)d_in[1];
    const void*  ei     = d_in[2];
    const void*  batch  = d_in[3];

    // num_nodes may or may not appear as a device input at index 4.
    // node_W is (1,C) = 128 elements; a num_nodes scalar is 1 element.
    int wbase = (in_sizes[4] == C) ? 4 : 5;

    const float* nodeW  = (const float*)d_in[wbase + 0];
    const float* nodeb  = (const float*)d_in[wbase + 1];
    const float* peW    = (const float*)d_in[wbase + 2];
    const float* peb    = (const float*)d_in[wbase + 3];
    const float* convW  = (const float*)d_in[wbase + 4];
    const float* convb  = (const float*)d_in[wbase + 5];
    const float* gamma  = (const float*)d_in[wbase + 6];
    const float* beta   = (const float*)d_in[wbase + 7];
    const float* W1     = (const float*)d_in[wbase + 8];
    const float* b1     = (const float*)d_in[wbase + 9];
    const float* W2     = (const float*)d_in[wbase + 10];
    const float* b2     = (const float*)d_in[wbase + 11];

    int N = in_sizes[0];          // x is (N,1)
    int E = in_sizes[2] / 2;      // edge_index is (2,E)

    cudaFuncSetAttribute(k_gemm, cudaFuncAttributeMaxDynamicSharedMemorySize, C * C * sizeof(float));

    k_detect<<<1, 32>>>((const unsigned int*)ei);
    k_zero<<<256, 256>>>(N);
    k_deg<<<1024, 256>>>(ei, E);
    k_gcount<<<256, 256>>>(batch, N);
    k_scan<<<1, 1024>>>(N);
    k_gscan<<<1, NG>>>();
    k_csrfill<<<1024, 256>>>(ei, E);
    k_encode<<<1024, 256>>>(x, pe, nodeW, nodeb, peW, peb, N);

    for (int l = 0; l < LAYERS; l++) {
        k_gemm<<<296, 256, C * C * sizeof(float)>>>(convW + (size_t)l * C * C, N);
        k_zerobn<<<1, 128>>>();
        k_aggregate<<<1480, 256>>>(convb + (size_t)l * C, N);
        k_bnfinal<<<1, 128>>>(gamma + (size_t)l * C, beta + (size_t)l * C, N);
        k_update<<<2048, 256>>>(N);
    }

    k_pool<<<NG, C>>>(N);
    k_head<<<NG, C>>>(W1, b1, W2, b2, (float*)d_out);
}

// round 4
// speedup vs baseline: 1.0278x; 1.0278x over previous
#include <cuda_runtime.h>
#include <cuda_fp16.h>

#define C       128
#define C4      32       // C/4 float4s per row
#define PEDIM   8
#define NG      512
#define LAYERS  3
#define BN_EPS  1e-5f
#define N_MAX   100352
#define E_MAX   1605632

// ---------------- scratch (static device globals; no allocation) ----------------
__device__ float g_h[(size_t)N_MAX * C];
__device__ float g_agg[(size_t)N_MAX * C];
__device__ uint2 g_t16[(size_t)N_MAX * 32];   // fp16 dinv-scaled t rows (256B/row)
__device__ int   g_deg[N_MAX];
__device__ int   g_fill[N_MAX];
__device__ float g_dinv[N_MAX];
__device__ int   g_csr_ptr[N_MAX + 1];
__device__ int   g_csr_col[E_MAX];
__device__ float g_bnsum[C];
__device__ float g_bnsq[C];
__device__ float g_scale[C];
__device__ float g_shift[C];
__device__ int   g_gcount[NG];
__device__ int   g_goff[NG];
__device__ float g_pooled[NG * C];
__device__ int   g_idx64;

// ---------------- f32x2 helpers (Blackwell packed fp32 FMA) ----------------
__device__ __forceinline__ unsigned long long f2pack(float lo, float hi) {
    unsigned long long r;
    asm("mov.b64 %0, {%1, %2};" : "=l"(r) : "f"(lo), "f"(hi));
    return r;
}
__device__ __forceinline__ void ffma2(unsigned long long& d, unsigned long long a, unsigned long long b) {
    asm("fma.rn.f32x2 %0, %1, %2, %0;" : "+l"(d) : "l"(a), "l"(b));
}
__device__ __forceinline__ float2 f2unpack(unsigned long long v) {
    float2 f;
    asm("mov.b64 {%0, %1}, %2;" : "=f"(f.x), "=f"(f.y) : "l"(v));
    return f;
}
// one A scalar against 4 channels (two f32x2 weight pairs)
__device__ __forceinline__ void gstep(float a, unsigned long long w01, unsigned long long w23,
                                      unsigned long long& d0, unsigned long long& d1) {
    unsigned long long ad = f2pack(a, a);
    ffma2(d0, ad, w01);
    ffma2(d1, ad, w23);
}

// ---------------- index helpers ----------------
__device__ __forceinline__ int load_idx(const void* p, long long i) {
    if (g_idx64) return (int)((const long long*)p)[i];
    return ((const int*)p)[i];
}

__global__ void k_detect(const unsigned int* w) {
    if (threadIdx.x == 0 && blockIdx.x == 0) {
        int z = 0;
        for (int i = 0; i < 64; i++) if (w[2 * i + 1] == 0u) z++;
        g_idx64 = (z >= 48) ? 1 : 0;
    }
}

__global__ void k_zero(int N) {
    int stride = gridDim.x * blockDim.x;
    for (int i = blockIdx.x * blockDim.x + threadIdx.x; i < N; i += stride) {
        g_deg[i] = 0; g_fill[i] = 0;
    }
    for (int i = blockIdx.x * blockDim.x + threadIdx.x; i < NG; i += stride) {
        g_gcount[i] = 0;
    }
}

__global__ void k_deg(const void* ei, int E) {
    int stride = gridDim.x * blockDim.x;
    for (int e = blockIdx.x * blockDim.x + threadIdx.x; e < E; e += stride) {
        int r = load_idx(ei, e);
        atomicAdd(&g_deg[r], 1);
    }
}

__global__ void k_gcount(const void* batch, int N) {
    int stride = gridDim.x * blockDim.x;
    for (int i = blockIdx.x * blockDim.x + threadIdx.x; i < N; i += stride) {
        int g = load_idx(batch, i);
        atomicAdd(&g_gcount[g], 1);
    }
}

__global__ void k_scan(int N) {
    __shared__ int ssum[1024];
    int t = threadIdx.x;
    int chunk = (N + 1023) >> 10;
    int lo = t * chunk;
    int hi = lo + chunk; if (hi > N) hi = N; if (lo > N) lo = N;
    int s = 0;
    for (int i = lo; i < hi; i++) {
        int d = g_deg[i];
        s += d;
        g_dinv[i] = (d > 0) ? rsqrtf((float)d) : 0.f;
    }
    ssum[t] = s;
    __syncthreads();
    for (int off = 1; off < 1024; off <<= 1) {
        int v = (t >= off) ? ssum[t - off] : 0;
        __syncthreads();
        ssum[t] += v;
        __syncthreads();
    }
    int run = (t == 0) ? 0 : ssum[t - 1];
    for (int i = lo; i < hi; i++) {
        g_csr_ptr[i] = run;
        run += g_deg[i];
    }
    if (t == 0) g_csr_ptr[N] = ssum[1023];
}

__global__ void k_gscan() {
    __shared__ int s[NG];
    int t = threadIdx.x;
    s[t] = g_gcount[t];
    __syncthreads();
    for (int off = 1; off < NG; off <<= 1) {
        int v = (t >= off) ? s[t - off] : 0;
        __syncthreads();
        s[t] += v;
        __syncthreads();
    }
    g_goff[t] = (t == 0) ? 0 : s[t - 1];
}

__global__ void k_csrfill(const void* ei, int E) {
    int stride = gridDim.x * blockDim.x;
    for (int e = blockIdx.x * blockDim.x + threadIdx.x; e < E; e += stride) {
        int r = load_idx(ei, e);
        int c = load_idx(ei, (long long)E + e);
        int pos = g_csr_ptr[r] + atomicAdd(&g_fill[r], 1);
        g_csr_col[pos] = c;
    }
}

// h0 = x @ node_W + node_b + pe @ pe_W + pe_b
__global__ void k_encode(const float* __restrict__ x, const float* __restrict__ pe,
                         const float* __restrict__ nW, const float* __restrict__ nb,
                         const float* __restrict__ pW, const float* __restrict__ pb, int N) {
    const float4* nW4 = (const float4*)nW;
    const float4* nb4 = (const float4*)nb;
    const float4* pW4 = (const float4*)pW;
    const float4* pb4 = (const float4*)pb;
    float4* H4 = (float4*)g_h;
    int total = N * C4;
    int stride = gridDim.x * blockDim.x;
    for (int i = blockIdx.x * blockDim.x + threadIdx.x; i < total; i += stride) {
        int n = i >> 5, q = i & 31;
        float xv = __ldg(&x[n]);
        float4 b0 = __ldg(&nb4[q]);
        float4 b1 = __ldg(&pb4[q]);
        float4 w  = __ldg(&nW4[q]);
        float4 a;
        a.x = b0.x + b1.x + xv * w.x;
        a.y = b0.y + b1.y + xv * w.y;
        a.z = b0.z + b1.z + xv * w.z;
        a.w = b0.w + b1.w + xv * w.w;
        #pragma unroll
        for (int k = 0; k < PEDIM; k++) {
            float pv = __ldg(&pe[(size_t)n * PEDIM + k]);
            float4 pw = __ldg(&pW4[k * C4 + q]);
            a.x = fmaf(pv, pw.x, a.x);
            a.y = fmaf(pv, pw.y, a.y);
            a.z = fmaf(pv, pw.z, a.z);
            a.w = fmaf(pv, pw.w, a.w);
        }
        H4[i] = a;
    }
}

// t = h @ W. Epilogue: g_agg[n] = t + bias (fp32 self term),
//                     g_t16[n] = fp16(dinv[n] * t)  (for neighbor gathers).
// W in SMEM; f32x2 packed FMAs; 4-row register blocking per warp.
__global__ void __launch_bounds__(256) k_gemm(const float* __restrict__ W,
                                              const float* __restrict__ bias, int N) {
    extern __shared__ float Ws[];
    const float4* W4 = (const float4*)W;
    float4* Ws4 = (float4*)Ws;
    for (int i = threadIdx.x; i < C * C4; i += 256) Ws4[i] = __ldg(&W4[i]);
    __syncthreads();
    const double* Wsd = (const double*)Ws;   // f32 pair view: index k*64 + c/2

    int warp = threadIdx.x >> 5, lane = threadIdx.x & 31;
    int warps_total = gridDim.x * 8;
    const float4* A4 = (const float4*)g_h;
    float4* AG4 = (float4*)g_agg;
    uint2* T16 = g_t16;
    float4 bias4 = __ldg(&((const float4*)bias)[lane]);
    int wp = lane << 1;   // weight pair base for this lane's 4 channels

    for (int r0 = (blockIdx.x * 8 + warp) * 4; r0 < N; r0 += warps_total * 4) {
        int nr = N - r0; if (nr > 4) nr = 4;
        const float4* Ar0 = A4 + (size_t)r0 * C4;
        if (nr == 4) {
            unsigned long long c00 = 0, c01 = 0, c10 = 0, c11 = 0;
            unsigned long long c20 = 0, c21 = 0, c30 = 0, c31 = 0;
            #pragma unroll
            for (int kk = 0; kk < 32; kk++) {
                float4 a0 = __ldg(&Ar0[kk]);
                float4 a1 = __ldg(&Ar0[C4 + kk]);
                float4 a2 = __ldg(&Ar0[2 * C4 + kk]);
                float4 a3 = __ldg(&Ar0[3 * C4 + kk]);
                int kb = kk * 4;
                unsigned long long w01, w23;
                w01 = __double_as_longlong(Wsd[(size_t)(kb + 0) * 64 + wp]);
                w23 = __double_as_longlong(Wsd[(size_t)(kb + 0) * 64 + wp + 1]);
                gstep(a0.x, w01, w23, c00, c01); gstep(a1.x, w01, w23, c10, c11);
                gstep(a2.x, w01, w23, c20, c21); gstep(a3.x, w01, w23, c30, c31);
                w01 = __double_as_longlong(Wsd[(size_t)(kb + 1) * 64 + wp]);
                w23 = __double_as_longlong(Wsd[(size_t)(kb + 1) * 64 + wp + 1]);
                gstep(a0.y, w01, w23, c00, c01); gstep(a1.y, w01, w23, c10, c11);
                gstep(a2.y, w01, w23, c20, c21); gstep(a3.y, w01, w23, c30, c31);
                w01 = __double_as_longlong(Wsd[(size_t)(kb + 2) * 64 + wp]);
                w23 = __double_as_longlong(Wsd[(size_t)(kb + 2) * 64 + wp + 1]);
                gstep(a0.z, w01, w23, c00, c01); gstep(a1.z, w01, w23, c10, c11);
                gstep(a2.z, w01, w23, c20, c21); gstep(a3.z, w01, w23, c30, c31);
                w01 = __double_as_longlong(Wsd[(size_t)(kb + 3) * 64 + wp]);
                w23 = __double_as_longlong(Wsd[(size_t)(kb + 3) * 64 + wp + 1]);
                gstep(a0.w, w01, w23, c00, c01); gstep(a1.w, w01, w23, c10, c11);
                gstep(a2.w, w01, w23, c20, c21); gstep(a3.w, w01, w23, c30, c31);
            }
            #pragma unroll
            for (int i = 0; i < 4; i++) {
                float2 lo, hi;
                if (i == 0) { lo = f2unpack(c00); hi = f2unpack(c01); }
                else if (i == 1) { lo = f2unpack(c10); hi = f2unpack(c11); }
                else if (i == 2) { lo = f2unpack(c20); hi = f2unpack(c21); }
                else { lo = f2unpack(c30); hi = f2unpack(c31); }
                float4 t; t.x = lo.x; t.y = lo.y; t.z = hi.x; t.w = hi.y;
                float dv = __ldg(&g_dinv[r0 + i]);
                float4 o;
                o.x = t.x + bias4.x; o.y = t.y + bias4.y;
                o.z = t.z + bias4.z; o.w = t.w + bias4.w;
                AG4[(size_t)(r0 + i) * C4 + lane] = o;
                __half2 hl = __floats2half2_rn(t.x * dv, t.y * dv);
                __half2 hh = __floats2half2_rn(t.z * dv, t.w * dv);
                uint2 u;
                u.x = *reinterpret_cast<unsigned int*>(&hl);
                u.y = *reinterpret_cast<unsigned int*>(&hh);
                T16[(size_t)(r0 + i) * 32 + lane] = u;
            }
        } else {
            for (int i = 0; i < nr; i++) {
                const float4* Arow = Ar0 + (size_t)i * C4;
                unsigned long long d0 = 0, d1 = 0;
                #pragma unroll
                for (int kk = 0; kk < 32; kk++) {
                    float4 av = __ldg(&Arow[kk]);
                    int kb = kk * 4;
                    unsigned long long w01, w23;
                    w01 = __double_as_longlong(Wsd[(size_t)(kb + 0) * 64 + wp]);
                    w23 = __double_as_longlong(Wsd[(size_t)(kb + 0) * 64 + wp + 1]);
                    gstep(av.x, w01, w23, d0, d1);
                    w01 = __double_as_longlong(Wsd[(size_t)(kb + 1) * 64 + wp]);
                    w23 = __double_as_longlong(Wsd[(size_t)(kb + 1) * 64 + wp + 1]);
                    gstep(av.y, w01, w23, d0, d1);
                    w01 = __double_as_longlong(Wsd[(size_t)(kb + 2) * 64 + wp]);
                    w23 = __double_as_longlong(Wsd[(size_t)(kb + 2) * 64 + wp + 1]);
                    gstep(av.z, w01, w23, d0, d1);
                    w01 = __double_as_longlong(Wsd[(size_t)(kb + 3) * 64 + wp]);
                    w23 = __double_as_longlong(Wsd[(size_t)(kb + 3) * 64 + wp + 1]);
                    gstep(av.w, w01, w23, d0, d1);
                }
                float2 lo = f2unpack(d0), hi = f2unpack(d1);
                float4 t; t.x = lo.x; t.y = lo.y; t.z = hi.x; t.w = hi.y;
                float dv = __ldg(&g_dinv[r0 + i]);
                float4 o;
                o.x = t.x + bias4.x; o.y = t.y + bias4.y;
                o.z = t.z + bias4.z; o.w = t.w + bias4.w;
                AG4[(size_t)(r0 + i) * C4 + lane] = o;
                __half2 hl = __floats2half2_rn(t.x * dv, t.y * dv);
                __half2 hh = __floats2half2_rn(t.z * dv, t.w * dv);
                uint2 u;
                u.x = *reinterpret_cast<unsigned int*>(&hl);
                u.y = *reinterpret_cast<unsigned int*>(&hh);
                T16[(size_t)(r0 + i) * 32 + lane] = u;
            }
        }
    }
}

__global__ void k_zerobn() {
    if (threadIdx.x < C) { g_bnsum[threadIdx.x] = 0.f; g_bnsq[threadIdx.x] = 0.f; }
}

__device__ __forceinline__ void addh4(float4& g, uint2 u) {
    __half2 h0 = *reinterpret_cast<__half2*>(&u.x);
    __half2 h1 = *reinterpret_cast<__half2*>(&u.y);
    float2 f0 = __half22float2(h0);
    float2 f1 = __half22float2(h1);
    g.x += f0.x; g.y += f0.y; g.z += f1.x; g.w += f1.y;
}

// agg[n] = (t[n]+bias)  [already seeded by gemm]  + dinv[n] * sum t16[col]
// fused BN partial stats
__global__ void __launch_bounds__(256) k_aggregate(int N) {
    __shared__ float ssum[C];
    __shared__ float ssq[C];
    if (threadIdx.x < C) { ssum[threadIdx.x] = 0.f; ssq[threadIdx.x] = 0.f; }
    __syncthreads();

    int warp = threadIdx.x >> 5, lane = threadIdx.x & 31;
    int warps_total = gridDim.x * 8;
    const uint2* T16 = g_t16;
    float4* A4 = (float4*)g_agg;

    float4 ps = make_float4(0.f, 0.f, 0.f, 0.f);
    float4 pq = make_float4(0.f, 0.f, 0.f, 0.f);

    for (int n = blockIdx.x * 8 + warp; n < N; n += warps_total) {
        int s = g_csr_ptr[n], e = g_csr_ptr[n + 1];
        float4 g = make_float4(0.f, 0.f, 0.f, 0.f);
        int j = s;
        for (; j + 4 <= e; j += 4) {
            int c0 = __ldg(&g_csr_col[j]);
            int c1 = __ldg(&g_csr_col[j + 1]);
            int c2 = __ldg(&g_csr_col[j + 2]);
            int c3 = __ldg(&g_csr_col[j + 3]);
            uint2 u0 = __ldg(&T16[(size_t)c0 * 32 + lane]);
            uint2 u1 = __ldg(&T16[(size_t)c1 * 32 + lane]);
            uint2 u2 = __ldg(&T16[(size_t)c2 * 32 + lane]);
            uint2 u3 = __ldg(&T16[(size_t)c3 * 32 + lane]);
            addh4(g, u0); addh4(g, u1); addh4(g, u2); addh4(g, u3);
        }
        for (; j < e; j++) {
            int ci = __ldg(&g_csr_col[j]);
            uint2 u = __ldg(&T16[(size_t)ci * 32 + lane]);
            addh4(g, u);
        }
        float dv = __ldg(&g_dinv[n]);
        float4 acc = A4[(size_t)n * C4 + lane];
        acc.x = fmaf(dv, g.x, acc.x); acc.y = fmaf(dv, g.y, acc.y);
        acc.z = fmaf(dv, g.z, acc.z); acc.w = fmaf(dv, g.w, acc.w);
        A4[(size_t)n * C4 + lane] = acc;
        ps.x += acc.x; ps.y += acc.y; ps.z += acc.z; ps.w += acc.w;
        pq.x = fmaf(acc.x, acc.x, pq.x); pq.y = fmaf(acc.y, acc.y, pq.y);
        pq.z = fmaf(acc.z, acc.z, pq.z); pq.w = fmaf(acc.w, acc.w, pq.w);
    }
    int c0 = lane * 4;
    atomicAdd(&ssum[c0 + 0], ps.x); atomicAdd(&ssum[c0 + 1], ps.y);
    atomicAdd(&ssum[c0 + 2], ps.z); atomicAdd(&ssum[c0 + 3], ps.w);
    atomicAdd(&ssq[c0 + 0], pq.x);  atomicAdd(&ssq[c0 + 1], pq.y);
    atomicAdd(&ssq[c0 + 2], pq.z);  atomicAdd(&ssq[c0 + 3], pq.w);
    __syncthreads();
    if (threadIdx.x < C) {
        atomicAdd(&g_bnsum[threadIdx.x], ssum[threadIdx.x]);
        atomicAdd(&g_bnsq[threadIdx.x],  ssq[threadIdx.x]);
    }
}

__global__ void k_bnfinal(const float* __restrict__ gamma, const float* __restrict__ beta, int N) {
    int c = threadIdx.x;
    if (c < C) {
        float invN = 1.f / (float)N;
        float mu = g_bnsum[c] * invN;
        float var = g_bnsq[c] * invN - mu * mu;
        if (var < 0.f) var = 0.f;
        float a = __ldg(&gamma[c]) * rsqrtf(var + BN_EPS);
        g_scale[c] = a;
        g_shift[c] = __ldg(&beta[c]) - mu * a;
    }
}

// h += relu(agg * scale + shift)   (layers 0..L-2)
__global__ void k_update(int N) {
    const float4* A4 = (const float4*)g_agg;
    float4* H4 = (float4*)g_h;
    const float4* sc4 = (const float4*)g_scale;
    const float4* sh4 = (const float4*)g_shift;
    int total = N * C4;
    int stride = gridDim.x * blockDim.x;
    for (int i = blockIdx.x * blockDim.x + threadIdx.x; i < total; i += stride) {
        int q = i & 31;
        float4 a = __ldg(&sc4[q]);
        float4 s = __ldg(&sh4[q]);
        float4 av = A4[i];
        float4 hv = H4[i];
        float rx = fmaf(av.x, a.x, s.x);
        float ry = fmaf(av.y, a.y, s.y);
        float rz = fmaf(av.z, a.z, s.z);
        float rw = fmaf(av.w, a.w, s.w);
        hv.x += rx > 0.f ? rx : 0.f;
        hv.y += ry > 0.f ? ry : 0.f;
        hv.z += rz > 0.f ? rz : 0.f;
        hv.w += rw > 0.f ? rw : 0.f;
        H4[i] = hv;
    }
}

// pooling with fused final-layer update: mean over nodes of
// h[i,c] + relu(agg[i,c]*scale[c]+shift[c])
__global__ void k_pool_fused(int N) {
    int g = blockIdx.x;
    int c = threadIdx.x;
    int start = g_goff[g];
    int cnt = g_gcount[g];
    float a = g_scale[c], sh = g_shift[c];
    float s = 0.f;
    const float* H = g_h;
    const float* A = g_agg;
    for (int i = 0; i < cnt; i++) {
        size_t off = (size_t)(start + i) * C + c;
        float r = fmaf(A[off], a, sh);
        s += H[off] + (r > 0.f ? r : 0.f);
    }
    g_pooled[g * C + c] = s / fmaxf((float)cnt, 1.f);
}

// out[g] = relu(pooled @ W1 + b1) @ W2 + b2
__global__ void k_head(const float* __restrict__ W1, const float* __restrict__ b1,
                       const float* __restrict__ W2, const float* __restrict__ b2,
                       float* __restrict__ out) {
    __shared__ float sp[C];
    __shared__ float red[4];
    int g = blockIdx.x;
    int j = threadIdx.x;
    sp[j] = g_pooled[g * C + j];
    __syncthreads();
    float acc = __ldg(&b1[j]);
    #pragma unroll 8
    for (int k = 0; k < C; k++) {
        acc = fmaf(sp[k], __ldg(&W1[k * C + j]), acc);
    }
    float hid = acc > 0.f ? acc : 0.f;
    float v = hid * __ldg(&W2[j]);
    #pragma unroll
    for (int o = 16; o > 0; o >>= 1) v += __shfl_down_sync(0xffffffffu, v, o);
    if ((j & 31) == 0) red[j >> 5] = v;
    __syncthreads();
    if (j == 0) out[g] = red[0] + red[1] + red[2] + red[3] + __ldg(&b2[0]);
}

// ---------------- launch ----------------
extern "C" void kernel_launch(void* const* d_in, const int* in_sizes, int n_in,
                              void* d_out, int out_size) {
    const float* x      = (const float*)d_in[0];
    const float* pe     = (const float*)d_in[1];
    const void*  ei     = d_in[2];
    const void*  batch  = d_in[3];

    // num_nodes may or may not appear as a device input at index 4.
    int wbase = (in_sizes[4] == C) ? 4 : 5;

    const float* nodeW  = (const float*)d_in[wbase + 0];
    const float* nodeb  = (const float*)d_in[wbase + 1];
    const float* peW    = (const float*)d_in[wbase + 2];
    const float* peb    = (const float*)d_in[wbase + 3];
    const float* convW  = (const float*)d_in[wbase + 4];
    const float* convb  = (const float*)d_in[wbase + 5];
    const float* gamma  = (const float*)d_in[wbase + 6];
    const float* beta   = (const float*)d_in[wbase + 7];
    const float* W1     = (const float*)d_in[wbase + 8];
    const float* b1     = (const float*)d_in[wbase + 9];
    const float* W2     = (const float*)d_in[wbase + 10];
    const float* b2     = (const float*)d_in[wbase + 11];

    int N = in_sizes[0];          // x is (N,1)
    int E = in_sizes[2] / 2;      // edge_index is (2,E)

    cudaFuncSetAttribute(k_gemm, cudaFuncAttributeMaxDynamicSharedMemorySize, C * C * sizeof(float));

    k_detect<<<1, 32>>>((const unsigned int*)ei);
    k_zero<<<256, 256>>>(N);
    k_deg<<<1024, 256>>>(ei, E);
    k_gcount<<<256, 256>>>(batch, N);
    k_scan<<<1, 1024>>>(N);
    k_gscan<<<1, NG>>>();
    k_csrfill<<<1024, 256>>>(ei, E);
    k_encode<<<1024, 256>>>(x, pe, nodeW, nodeb, peW, peb, N);

    for (int l = 0; l < LAYERS; l++) {
        k_gemm<<<444, 256, C * C * sizeof(float)>>>(convW + (size_t)l * C * C,
                                                    convb + (size_t)l * C, N);
        k_zerobn<<<1, 128>>>();
        k_aggregate<<<1480, 256>>>(N);
        k_bnfinal<<<1, 128>>>(gamma + (size_t)l * C, beta + (size_t)l * C, N);
        if (l < LAYERS - 1) k_update<<<2048, 256>>>(N);
    }

    k_pool_fused<<<NG, C>>>(N);
    k_head<<<NG, C>>>(W1, b1, W2, b2, (float*)d_out);
}